// round 14
// baseline (speedup 1.0000x reference)
#include <cuda_runtime.h>
#include <cstdint>
#include <math.h>

#define BB   4096
#define SS   50
#define HIDD 256
#define NHH  4
#define HDD  64
#define FBB  26
#define PPER 208   // NH*FB*2

typedef unsigned long long u64;

// ---------------- scratch ----------------
__device__ __align__(16) float g_ctx[BB * HIDD];
__device__ __align__(16) float g_h[BB * HIDD];
__device__ __align__(16) float g_fb[BB * PPER];

// ---------------- helpers ----------------
__device__ __forceinline__ void ffma2(u64 &d, u64 a, u64 b) {
    asm("fma.rn.f32x2 %0, %1, %2, %0;" : "+l"(d) : "l"(a), "l"(b));
}
__device__ __forceinline__ u64 pack2(float lo, float hi) {
    u64 r; asm("mov.b64 %0, {%1, %2};" : "=l"(r) : "f"(lo), "f"(hi)); return r;
}
__device__ __forceinline__ void unpack2(u64 v, float &lo, float &hi) {
    asm("mov.b64 {%0, %1}, %2;" : "=f"(lo), "=f"(hi) : "l"(v));
}
__device__ __forceinline__ float gelu_exact(float x) {
    return 0.5f * x * (1.0f + erff(x * 0.70710678118654752f));
}
__device__ __forceinline__ void cpa16(uint32_t s, const void* g) {
    asm volatile("cp.async.cg.shared.global [%0], [%1], 16;" :: "r"(s), "l"(g));
}
__device__ __forceinline__ void cpa_commit() {
    asm volatile("cp.async.commit_group;");
}
__device__ __forceinline__ void cpa_wait0() {
    asm volatile("cp.async.wait_group 0;" ::: "memory");
}

// ---------------- K1: attr_ctx = mean over S (80% DRAM — at the wall) --------
__global__ __launch_bounds__(256) void k_ctx(const float* __restrict__ attr) {
    int idx = blockIdx.x * 256 + threadIdx.x;
    int b  = idx >> 6;
    int c4 = idx & 63;
    const float4* p = reinterpret_cast<const float4*>(attr + (size_t)b * SS * HIDD) + c4;
    float sx = 0.f, sy = 0.f, sz = 0.f, sw = 0.f;
    #pragma unroll
    for (int t = 0; t < SS; t++) {
        float4 v = p[(size_t)t * (HIDD / 4)];
        sx += v.x; sy += v.y; sz += v.z; sw += v.w;
    }
    float4 o; o.x = sx * 0.02f; o.y = sy * 0.02f; o.z = sz * 0.02f; o.w = sw * 0.02f;
    reinterpret_cast<float4*>(g_ctx)[idx] = o;
}

// ---------------- 64x64x16 tiled GEMMs — f32x2 micro-kernel -------------------
// A pairs (a_i, a_i+1) are native u64 in As[k][m]; B duplicated at store time
// so (b_j, b_j) pairs are native u64. Inner loop: 3 LDS.128 + 8 FFMA2 per k.
#define GPAD 68

__global__ __launch_bounds__(256) void k_g1(const float* __restrict__ w1,
                                            const float* __restrict__ b1) {
    __shared__ __align__(16) float As[16 * GPAD];   // [k][m]
    __shared__ __align__(16) float Bs[16 * 128];    // [k][2*n] duplicated
    int bm0 = blockIdx.x * 64;
    int n0g = blockIdx.y * 64;
    int tid = threadIdx.x;
    int am = tid >> 2, akq = (tid & 3) * 4;
    int bk = tid >> 4, bn  = (tid & 15) * 4;
    int m0 = (tid >> 4) * 4, n0 = (tid & 15) * 4;

    float4 binit = __ldg(reinterpret_cast<const float4*>(b1 + n0g + n0));
    u64 acc2[2][4];   // [row-pair][col]; lanes = rows m0+2ip, m0+2ip+1
    acc2[0][0] = acc2[1][0] = pack2(binit.x, binit.x);
    acc2[0][1] = acc2[1][1] = pack2(binit.y, binit.y);
    acc2[0][2] = acc2[1][2] = pack2(binit.z, binit.z);
    acc2[0][3] = acc2[1][3] = pack2(binit.w, binit.w);

    float4 ra = __ldg(reinterpret_cast<const float4*>(
        g_ctx + (bm0 + am) * HIDD + akq));
    float4 rb = __ldg(reinterpret_cast<const float4*>(
        w1 + bk * HIDD + n0g + bn));

    for (int kt = 0; kt < HIDD; kt += 16) {
        As[(akq + 0) * GPAD + am] = ra.x;
        As[(akq + 1) * GPAD + am] = ra.y;
        As[(akq + 2) * GPAD + am] = ra.z;
        As[(akq + 3) * GPAD + am] = ra.w;
        *reinterpret_cast<float4*>(&Bs[bk * 128 + 2 * bn])     =
            make_float4(rb.x, rb.x, rb.y, rb.y);
        *reinterpret_cast<float4*>(&Bs[bk * 128 + 2 * bn + 4]) =
            make_float4(rb.z, rb.z, rb.w, rb.w);
        __syncthreads();
        if (kt + 16 < HIDD) {
            ra = __ldg(reinterpret_cast<const float4*>(
                g_ctx + (bm0 + am) * HIDD + kt + 16 + akq));
            rb = __ldg(reinterpret_cast<const float4*>(
                w1 + (kt + 16 + bk) * HIDD + n0g + bn));
        }
        #pragma unroll
        for (int k = 0; k < 16; k++) {
            ulonglong2 a2 = *reinterpret_cast<const ulonglong2*>(&As[k * GPAD + m0]);
            ulonglong2 bd01 = *reinterpret_cast<const ulonglong2*>(&Bs[k * 128 + 2 * n0]);
            ulonglong2 bd23 = *reinterpret_cast<const ulonglong2*>(&Bs[k * 128 + 2 * n0 + 4]);
            ffma2(acc2[0][0], a2.x, bd01.x); ffma2(acc2[1][0], a2.y, bd01.x);
            ffma2(acc2[0][1], a2.x, bd01.y); ffma2(acc2[1][1], a2.y, bd01.y);
            ffma2(acc2[0][2], a2.x, bd23.x); ffma2(acc2[1][2], a2.y, bd23.x);
            ffma2(acc2[0][3], a2.x, bd23.y); ffma2(acc2[1][3], a2.y, bd23.y);
        }
        __syncthreads();
    }
    float accf[4][4];
    #pragma unroll
    for (int ip = 0; ip < 2; ip++)
        #pragma unroll
        for (int j = 0; j < 4; j++) {
            float lo, hi; unpack2(acc2[ip][j], lo, hi);
            accf[2 * ip][j] = lo; accf[2 * ip + 1][j] = hi;
        }
    #pragma unroll
    for (int i = 0; i < 4; i++) {
        float4 o;
        o.x = gelu_exact(accf[i][0]); o.y = gelu_exact(accf[i][1]);
        o.z = gelu_exact(accf[i][2]); o.w = gelu_exact(accf[i][3]);
        *reinterpret_cast<float4*>(&g_h[(bm0 + m0 + i) * HIDD + n0g + n0]) = o;
    }
}

__global__ __launch_bounds__(256) void k_g2(const float* __restrict__ w2,
                                            const float* __restrict__ b2,
                                            const float* __restrict__ bfil,
                                            const float* __restrict__ bbia) {
    __shared__ __align__(16) float As[16 * GPAD];
    __shared__ __align__(16) float Bs[16 * 128];
    int bm0 = blockIdx.x * 64;
    int n0g = blockIdx.y * 64;
    int tid = threadIdx.x;
    int am = tid >> 2, akq = (tid & 3) * 4;
    int bk = tid >> 4, bn  = (tid & 15) * 4;
    int m0 = (tid >> 4) * 4, n0 = (tid & 15) * 4;
    int col0 = n0g + n0;
    int bcol = n0g + bn;

    u64 acc2[2][4];
    #pragma unroll
    for (int j = 0; j < 4; j++) {
        float bv = (col0 + j < PPER) ? __ldg(&b2[col0 + j]) : 0.f;
        acc2[0][j] = acc2[1][j] = pack2(bv, bv);
    }

    float4 zero4 = make_float4(0.f, 0.f, 0.f, 0.f);
    float4 ra = __ldg(reinterpret_cast<const float4*>(
        g_h + (bm0 + am) * HIDD + akq));
    float4 rb = (bcol < PPER)
        ? __ldg(reinterpret_cast<const float4*>(w2 + bk * PPER + bcol))
        : zero4;

    for (int kt = 0; kt < HIDD; kt += 16) {
        As[(akq + 0) * GPAD + am] = ra.x;
        As[(akq + 1) * GPAD + am] = ra.y;
        As[(akq + 2) * GPAD + am] = ra.z;
        As[(akq + 3) * GPAD + am] = ra.w;
        *reinterpret_cast<float4*>(&Bs[bk * 128 + 2 * bn])     =
            make_float4(rb.x, rb.x, rb.y, rb.y);
        *reinterpret_cast<float4*>(&Bs[bk * 128 + 2 * bn + 4]) =
            make_float4(rb.z, rb.z, rb.w, rb.w);
        __syncthreads();
        if (kt + 16 < HIDD) {
            ra = __ldg(reinterpret_cast<const float4*>(
                g_h + (bm0 + am) * HIDD + kt + 16 + akq));
            rb = (bcol < PPER)
                ? __ldg(reinterpret_cast<const float4*>(
                      w2 + (kt + 16 + bk) * PPER + bcol))
                : zero4;
        }
        #pragma unroll
        for (int k = 0; k < 16; k++) {
            ulonglong2 a2 = *reinterpret_cast<const ulonglong2*>(&As[k * GPAD + m0]);
            ulonglong2 bd01 = *reinterpret_cast<const ulonglong2*>(&Bs[k * 128 + 2 * n0]);
            ulonglong2 bd23 = *reinterpret_cast<const ulonglong2*>(&Bs[k * 128 + 2 * n0 + 4]);
            ffma2(acc2[0][0], a2.x, bd01.x); ffma2(acc2[1][0], a2.y, bd01.x);
            ffma2(acc2[0][1], a2.x, bd01.y); ffma2(acc2[1][1], a2.y, bd01.y);
            ffma2(acc2[0][2], a2.x, bd23.x); ffma2(acc2[1][2], a2.y, bd23.x);
            ffma2(acc2[0][3], a2.x, bd23.y); ffma2(acc2[1][3], a2.y, bd23.y);
        }
        __syncthreads();
    }
    float accf[4][4];
    #pragma unroll
    for (int ip = 0; ip < 2; ip++)
        #pragma unroll
        for (int j = 0; j < 4; j++) {
            float lo, hi; unpack2(acc2[ip][j], lo, hi);
            accf[2 * ip][j] = lo; accf[2 * ip + 1][j] = hi;
        }
    #pragma unroll
    for (int j = 0; j < 4; j++) {
        int c = col0 + j;
        if (c < PPER) {
            int h = c / 52, rr = c % 52, fi = rr >> 1;
            float basef = __ldg(&bfil[h * FBB + fi]);
            float baseb = __ldg(&bbia[h * FBB + fi]);
            #pragma unroll
            for (int i = 0; i < 4; i++) {
                float v = (rr & 1) ? (baseb + accf[i][j])
                                   : (basef * (1.0f + accf[i][j]));
                g_fb[(bm0 + m0 + i) * PPER + c] = v;
            }
        }
    }
}

// ---------------- k_main helpers (templated, static coeff indexing) ----------
template<int I0, int NI, int PAR>
__device__ __forceinline__ void conv_pass(u64* acc, const float* xcol,
                                          const u64* cdh, int p) {
    u64 cc[13];
    #pragma unroll
    for (int j = 0; j < 13; j++) cc[j] = cdh[2 * j + PAR];
    #pragma unroll
    for (int e = 0; e < 25; e++) {
        int srow = 2 * e + PAR + p;
        if (2 * e + PAR + 1 >= 50) { if (srow >= 50) srow -= 50; }
        u64 xv = *reinterpret_cast<const u64*>(xcol + srow * HIDD);
        #pragma unroll
        for (int i = 0; i < NI; i++) {
            const int dd = ((2 * (I0 + i) - (2 * e + PAR)) % 50 + 50) % 50;
            const int f  = (dd <= 25) ? dd : (50 - dd);
            ffma2(acc[i], xv, cc[f >> 1]);
        }
    }
}

template<int I0, int NI>
__device__ __forceinline__ void acc_init(u64* acc, const float* bvs, int h, int p) {
    #pragma unroll
    for (int i = 0; i < NI; i++) {
        float bv = bvs[h * 50 + 2 * (I0 + i) + p];
        acc[i] = pack2(bv, bv);
    }
}

template<int I0, int NI>
__device__ __forceinline__ void wavelet_combine(u64* acc, const float* xs,
                                                const float* __restrict__ cw,
                                                int h, int d0, int p) {
    float sgn = p ? -1.0f : 1.0f;
    int dl = d0 & 63;
    #pragma unroll
    for (int i = 0; i < NI; i++) {
        int ia = I0 + i;
        float2 e = *reinterpret_cast<const float2*>(&xs[(2 * ia)     * HIDD + d0]);
        float2 o = *reinterpret_cast<const float2*>(&xs[(2 * ia + 1) * HIDD + d0]);
        float2 w = __ldg(reinterpret_cast<const float2*>(cw + h * (25 * HDD) + ia * HDD + dl));
        float ax = 0.5f * (e.x + o.x), ay = 0.5f * (e.y + o.y);
        float dx = 0.5f * (e.x - o.x) * w.x, dy = 0.5f * (e.y - o.y) * w.y;
        float wx = ax + sgn * dx, wy = ay + sgn * dy;
        float ix = p ? o.x : e.x;
        float iy = p ? o.y : e.y;
        float fx, fy; unpack2(acc[i], fx, fy);
        acc[i] = pack2(0.7f * wx + 0.3f * fx + ix,
                       0.7f * wy + 0.3f * fy + iy);
    }
}

template<int I0, int NI>
__device__ __forceinline__ void store_rows(const u64* acc, float* xs, int d0, int p) {
    #pragma unroll
    for (int i = 0; i < NI; i++)
        *reinterpret_cast<u64*>(&xs[(2 * (I0 + i) + p) * HIDD + d0]) = acc[i];
}

// ---------------- K4: 512 threads, 2 CTAs/SM (PROVEN; unchanged from R13) ----
// smem float offsets (16B-aligned where vector-accessed):
//   xs 0:12800 | cd 12800:208 | bvs 13008:200 | fbs 13208:208
//   ctab 13416:56(pad) | gs 13472:256 | bsv 13728:256  => 13984 floats
#define SMEM_FLOATS 13984

__global__ __launch_bounds__(512, 2) void k_main(const float* __restrict__ item,
                                                 const float* __restrict__ cw,
                                                 const float* __restrict__ gamma,
                                                 const float* __restrict__ beta,
                                                 float* __restrict__ out) {
    extern __shared__ float sm[];
    float* xs   = sm;
    float* cd   = sm + 12800;
    float* bvs  = sm + 13008;
    float* fbs  = sm + 13208;
    float* ctab = sm + 13416;   // 56 floats (50 used, 6 pad for alignment)
    float* gs   = sm + 13472;   // 16B-aligned
    float* bsv  = sm + 13728;   // 16B-aligned

    int b   = blockIdx.x;
    int tid = threadIdx.x;
    const float* itemb = item + (size_t)b * SS * HIDD;

    // ---- stage: xs via cp.async (latency hidden under coeff compute) ----
    {
        uint32_t xa = (uint32_t)__cvta_generic_to_shared(xs);
        for (int i = tid; i < SS * HIDD / 4; i += 512)
            cpa16(xa + i * 16, itemb + i * 4);
        cpa_commit();
    }
    if (tid < PPER) fbs[tid] = g_fb[b * PPER + tid];
    if (tid < 50)   ctab[tid] = cospif((float)tid * (1.0f / 25.0f));
    if (tid < HIDD) { gs[tid] = gamma[tid]; bsv[tid] = beta[tid]; }
    __syncthreads();   // fbs/ctab visible for coeff compute (xs still in flight)

    // ---- circulant coeffs (even-symmetric, m=0..25, duplicated f32x2) + bias ----
    if (tid < 104) {
        int h = tid / 26, m = tid % 26;
        const float* fh = fbs + h * 52;
        float cacc = 0.f;
        int idx = 0;
        #pragma unroll
        for (int k = 0; k < 26; k++) {
            float w = (k == 0 || k == 25) ? 1.0f : 2.0f;
            cacc += fh[2 * k] * w * ctab[idx];
            idx += m; if (idx >= 50) idx -= 50;
        }
        reinterpret_cast<float2*>(cd)[h * 26 + m] = make_float2(cacc * 0.02f, cacc * 0.02f);
    }
    if (tid < 200) {
        int h = tid / 50, m = tid % 50;
        const float* fh = fbs + h * 52;
        float bacc = 0.f;
        int idx = 0;
        #pragma unroll
        for (int k = 0; k < 26; k++) {
            float w = (k == 0 || k == 25) ? 1.0f : 2.0f;
            bacc += fh[2 * k + 1] * w * ctab[idx];
            idx += m; if (idx >= 50) idx -= 50;
        }
        bvs[h * 50 + m] = bacc * 0.14142135623730951f;
    }
    cpa_wait0();       // xs arrival
    __syncthreads();   // coeffs + xs visible to all

    // ---- thread mapping: tid = rh*256 + p*128 + dp ----
    int dp = tid & 127;
    int p  = (tid >> 7) & 1;
    int rh = tid >> 8;            // warp-uniform
    int d0 = dp * 2;
    int h  = dp >> 5;

    const u64*   cdh  = reinterpret_cast<const u64*>(cd) + h * 26;
    const float* xcol = xs + d0;

    u64 acc[13];
    if (rh == 0) {
        acc_init<0, 13>(acc, bvs, h, p);
        conv_pass<0, 13, 0>(acc, xcol, cdh, p);
    } else {
        acc_init<13, 12>(acc, bvs, h, p);
        conv_pass<13, 12, 0>(acc, xcol, cdh, p);
    }
    __syncthreads();   // uniform; scheduling fence between coefficient banks
    if (rh == 0) conv_pass<0, 13, 1>(acc, xcol, cdh, p);
    else         conv_pass<13, 12, 1>(acc, xcol, cdh, p);

    // ---- wavelet + combine + residual ----
    if (rh == 0) wavelet_combine<0, 13>(acc, xs, cw, h, d0, p);
    else         wavelet_combine<13, 12>(acc, xs, cw, h, d0, p);

    __syncthreads();
    if (rh == 0) store_rows<0, 13>(acc, xs, d0, p);
    else         store_rows<13, 12>(acc, xs, d0, p);
    __syncthreads();

    // ---- LayerNorm: 16 warps over 50 rows, float4 lane-consecutive ----
    int wid = tid >> 5, lane = tid & 31;
    const float4* xs4 = reinterpret_cast<const float4*>(xs);
    const float4* gs4 = reinterpret_cast<const float4*>(gs);
    const float4* bs4 = reinterpret_cast<const float4*>(bsv);
    float4* outb4 = reinterpret_cast<float4*>(out + (size_t)b * SS * HIDD);
    float4 ga = gs4[lane];
    float4 gb = gs4[32 + lane];
    float4 ba = bs4[lane];
    float4 bb = bs4[32 + lane];
    for (int t = wid; t < SS; t += 16) {
        float4 va = xs4[t * 64 + lane];
        float4 vb = xs4[t * 64 + 32 + lane];
        float s1 = va.x + va.y + va.z + va.w + vb.x + vb.y + vb.z + vb.w;
        float s2 = va.x * va.x + va.y * va.y + va.z * va.z + va.w * va.w
                 + vb.x * vb.x + vb.y * vb.y + vb.z * vb.z + vb.w * vb.w;
        #pragma unroll
        for (int off = 16; off; off >>= 1) {
            s1 += __shfl_xor_sync(0xffffffffu, s1, off);
            s2 += __shfl_xor_sync(0xffffffffu, s2, off);
        }
        float mu  = s1 * (1.0f / 256.0f);
        float var = s2 * (1.0f / 256.0f) - mu * mu;
        float rs  = rsqrtf(var + 1e-12f);
        float4 oa, ob;
        oa.x = (va.x - mu) * rs * ga.x + ba.x;
        oa.y = (va.y - mu) * rs * ga.y + ba.y;
        oa.z = (va.z - mu) * rs * ga.z + ba.z;
        oa.w = (va.w - mu) * rs * ga.w + ba.w;
        ob.x = (vb.x - mu) * rs * gb.x + bb.x;
        ob.y = (vb.y - mu) * rs * gb.y + bb.y;
        ob.z = (vb.z - mu) * rs * gb.z + bb.z;
        ob.w = (vb.w - mu) * rs * gb.w + bb.w;
        outb4[t * 64 + lane]      = oa;
        outb4[t * 64 + 32 + lane] = ob;
    }
}

// ---------------- launcher ----------------
extern "C" void kernel_launch(void* const* d_in, const int* in_sizes, int n_in,
                              void* d_out, int out_size) {
    const float* item = (const float*)d_in[0];
    const float* attr = (const float*)d_in[1];
    const float* cw   = (const float*)d_in[2];
    const float* bfil = (const float*)d_in[3];
    const float* bbia = (const float*)d_in[4];
    const float* w1   = (const float*)d_in[5];
    const float* b1   = (const float*)d_in[6];
    const float* w2   = (const float*)d_in[7];
    const float* b2   = (const float*)d_in[8];
    const float* gam  = (const float*)d_in[9];
    const float* bet  = (const float*)d_in[10];
    float* out = (float*)d_out;

    cudaFuncSetAttribute(k_main, cudaFuncAttributeMaxDynamicSharedMemorySize,
                         SMEM_FLOATS * (int)sizeof(float));

    k_ctx<<<BB * (HIDD / 4) / 256, 256>>>(attr);
    k_g1<<<dim3(BB / 64, HIDD / 64), 256>>>(w1, b1);
    k_g2<<<dim3(BB / 64, 4), 256>>>(w2, b2, bfil, bbia);
    k_main<<<BB, 512, SMEM_FLOATS * (int)sizeof(float)>>>(item, cw, gam, bet, out);
}

// round 16
// speedup vs baseline: 1.2022x; 1.2022x over previous
#include <cuda_runtime.h>
#include <cstdint>
#include <math.h>

#define BB   4096
#define SS   50
#define HIDD 256
#define NHH  4
#define HDD  64
#define FBB  26
#define PPER 208   // NH*FB*2

typedef unsigned long long u64;

// ---------------- scratch ----------------
__device__ __align__(16) float g_ctx[BB * HIDD];
__device__ __align__(16) float g_h[BB * HIDD];
__device__ __align__(16) float g_fb[BB * PPER];

// ---------------- helpers ----------------
__device__ __forceinline__ void ffma2(u64 &d, u64 a, u64 b) {
    asm("fma.rn.f32x2 %0, %1, %2, %0;" : "+l"(d) : "l"(a), "l"(b));
}
__device__ __forceinline__ u64 pack2(float lo, float hi) {
    u64 r; asm("mov.b64 %0, {%1, %2};" : "=l"(r) : "f"(lo), "f"(hi)); return r;
}
__device__ __forceinline__ void unpack2(u64 v, float &lo, float &hi) {
    asm("mov.b64 {%0, %1}, %2;" : "=f"(lo), "=f"(hi) : "l"(v));
}
__device__ __forceinline__ float gelu_exact(float x) {
    return 0.5f * x * (1.0f + erff(x * 0.70710678118654752f));
}
__device__ __forceinline__ void cpa16(uint32_t s, const void* g) {
    asm volatile("cp.async.cg.shared.global [%0], [%1], 16;" :: "r"(s), "l"(g));
}
__device__ __forceinline__ void cpa_commit() {
    asm volatile("cp.async.commit_group;");
}
__device__ __forceinline__ void cpa_wait0() {
    asm volatile("cp.async.wait_group 0;" ::: "memory");
}

// ---------------- K1: attr_ctx = mean over S (80% DRAM — at the wall) --------
__global__ __launch_bounds__(256) void k_ctx(const float* __restrict__ attr) {
    int idx = blockIdx.x * 256 + threadIdx.x;
    int b  = idx >> 6;
    int c4 = idx & 63;
    const float4* p = reinterpret_cast<const float4*>(attr + (size_t)b * SS * HIDD) + c4;
    float sx = 0.f, sy = 0.f, sz = 0.f, sw = 0.f;
    #pragma unroll
    for (int t = 0; t < SS; t++) {
        float4 v = p[(size_t)t * (HIDD / 4)];
        sx += v.x; sy += v.y; sz += v.z; sw += v.w;
    }
    float4 o; o.x = sx * 0.02f; o.y = sy * 0.02f; o.z = sz * 0.02f; o.w = sw * 0.02f;
    reinterpret_cast<float4*>(g_ctx)[idx] = o;
}

// ---------------- 64x64 tiled GEMMs, k-tile 32, double-buffered cp.async ------
// Scalar fp32 micro-kernel (R13-proven). One barrier per k-iteration; B tiles
// stream via cp.async; A tiles staged one ahead through registers.
#define GPAD 68
#define NIT  (HIDD / 32)   // 8

__global__ __launch_bounds__(256) void k_g1(const float* __restrict__ w1,
                                            const float* __restrict__ b1) {
    __shared__ __align__(16) float As[2][32 * GPAD];   // [k][m]
    __shared__ __align__(16) float Bs[2][32 * 64];     // [k][n]
    int bm0 = blockIdx.x * 64;
    int n0g = blockIdx.y * 64;
    int tid = threadIdx.x;
    int am = tid >> 2, ak8 = (tid & 3) * 8;     // A-load: row am, k in [ak8, ak8+8)
    int bk = tid >> 4, bn  = (tid & 15) * 4;    // B-load: rows bk, bk+16; col bn
    int m0 = (tid >> 4) * 4, n0 = (tid & 15) * 4;

    float4 binit = __ldg(reinterpret_cast<const float4*>(b1 + n0g + n0));
    float acc[4][4];
    #pragma unroll
    for (int i = 0; i < 4; i++) {
        acc[i][0] = binit.x; acc[i][1] = binit.y;
        acc[i][2] = binit.z; acc[i][3] = binit.w;
    }

    const float* aSrc = g_ctx + (size_t)(bm0 + am) * HIDD;
    const float* bSrc = w1 + n0g + bn;

    // ---- prologue: tile 0 staged, tile 1 in flight ----
    float4 ra0 = __ldg(reinterpret_cast<const float4*>(aSrc + ak8));
    float4 ra1 = __ldg(reinterpret_cast<const float4*>(aSrc + ak8 + 4));
    #pragma unroll
    for (int j = 0; j < 4; j++) {
        As[0][(ak8 + j) * GPAD + am]     = (&ra0.x)[j];
        As[0][(ak8 + 4 + j) * GPAD + am] = (&ra1.x)[j];
    }
    cpa16((uint32_t)__cvta_generic_to_shared(&Bs[0][bk * 64 + bn]),
          bSrc + (size_t)bk * HIDD);
    cpa16((uint32_t)__cvta_generic_to_shared(&Bs[0][(bk + 16) * 64 + bn]),
          bSrc + (size_t)(bk + 16) * HIDD);
    cpa_commit();
    ra0 = __ldg(reinterpret_cast<const float4*>(aSrc + 32 + ak8));
    ra1 = __ldg(reinterpret_cast<const float4*>(aSrc + 32 + ak8 + 4));
    cpa_wait0();
    __syncthreads();

    for (int it = 0; it < NIT; it++) {
        int c = it & 1, o = c ^ 1;
        if (it + 1 < NIT) {
            #pragma unroll
            for (int j = 0; j < 4; j++) {
                As[o][(ak8 + j) * GPAD + am]     = (&ra0.x)[j];
                As[o][(ak8 + 4 + j) * GPAD + am] = (&ra1.x)[j];
            }
            int kt = (it + 1) * 32;
            cpa16((uint32_t)__cvta_generic_to_shared(&Bs[o][bk * 64 + bn]),
                  bSrc + (size_t)(kt + bk) * HIDD);
            cpa16((uint32_t)__cvta_generic_to_shared(&Bs[o][(bk + 16) * 64 + bn]),
                  bSrc + (size_t)(kt + 16 + bk) * HIDD);
            cpa_commit();
            if (it + 2 < NIT) {
                ra0 = __ldg(reinterpret_cast<const float4*>(aSrc + (it + 2) * 32 + ak8));
                ra1 = __ldg(reinterpret_cast<const float4*>(aSrc + (it + 2) * 32 + ak8 + 4));
            }
        }
        #pragma unroll
        for (int k = 0; k < 32; k++) {
            float4 a4 = *reinterpret_cast<const float4*>(&As[c][k * GPAD + m0]);
            float4 b4 = *reinterpret_cast<const float4*>(&Bs[c][k * 64 + n0]);
            acc[0][0] += a4.x * b4.x; acc[0][1] += a4.x * b4.y;
            acc[0][2] += a4.x * b4.z; acc[0][3] += a4.x * b4.w;
            acc[1][0] += a4.y * b4.x; acc[1][1] += a4.y * b4.y;
            acc[1][2] += a4.y * b4.z; acc[1][3] += a4.y * b4.w;
            acc[2][0] += a4.z * b4.x; acc[2][1] += a4.z * b4.y;
            acc[2][2] += a4.z * b4.z; acc[2][3] += a4.z * b4.w;
            acc[3][0] += a4.w * b4.x; acc[3][1] += a4.w * b4.y;
            acc[3][2] += a4.w * b4.z; acc[3][3] += a4.w * b4.w;
        }
        if (it + 1 < NIT) cpa_wait0();
        __syncthreads();
    }
    #pragma unroll
    for (int i = 0; i < 4; i++) {
        float4 o;
        o.x = gelu_exact(acc[i][0]); o.y = gelu_exact(acc[i][1]);
        o.z = gelu_exact(acc[i][2]); o.w = gelu_exact(acc[i][3]);
        *reinterpret_cast<float4*>(&g_h[(size_t)(bm0 + m0 + i) * HIDD + n0g + n0]) = o;
    }
}

__global__ __launch_bounds__(256) void k_g2(const float* __restrict__ w2,
                                            const float* __restrict__ b2,
                                            const float* __restrict__ bfil,
                                            const float* __restrict__ bbia) {
    __shared__ __align__(16) float As[2][32 * GPAD];
    __shared__ __align__(16) float Bs[2][32 * 64];
    int bm0 = blockIdx.x * 64;
    int n0g = blockIdx.y * 64;
    int tid = threadIdx.x;
    int am = tid >> 2, ak8 = (tid & 3) * 8;
    int bk = tid >> 4, bn  = (tid & 15) * 4;
    int m0 = (tid >> 4) * 4, n0 = (tid & 15) * 4;
    int col0 = n0g + n0;
    int bcol = n0g + bn;
    bool bvalid = (bcol < PPER);

    float acc[4][4];
    #pragma unroll
    for (int j = 0; j < 4; j++) {
        float bv = (col0 + j < PPER) ? __ldg(&b2[col0 + j]) : 0.f;
        #pragma unroll
        for (int i = 0; i < 4; i++) acc[i][j] = bv;
    }

    const float* aSrc = g_h + (size_t)(bm0 + am) * HIDD;
    const float* bSrc = w2 + bcol;

    // zero dead B columns once (cp.async never touches them)
    if (!bvalid) {
        float4 z = make_float4(0.f, 0.f, 0.f, 0.f);
        *reinterpret_cast<float4*>(&Bs[0][bk * 64 + bn]) = z;
        *reinterpret_cast<float4*>(&Bs[0][(bk + 16) * 64 + bn]) = z;
        *reinterpret_cast<float4*>(&Bs[1][bk * 64 + bn]) = z;
        *reinterpret_cast<float4*>(&Bs[1][(bk + 16) * 64 + bn]) = z;
    }

    // ---- prologue ----
    float4 ra0 = __ldg(reinterpret_cast<const float4*>(aSrc + ak8));
    float4 ra1 = __ldg(reinterpret_cast<const float4*>(aSrc + ak8 + 4));
    #pragma unroll
    for (int j = 0; j < 4; j++) {
        As[0][(ak8 + j) * GPAD + am]     = (&ra0.x)[j];
        As[0][(ak8 + 4 + j) * GPAD + am] = (&ra1.x)[j];
    }
    if (bvalid) {
        cpa16((uint32_t)__cvta_generic_to_shared(&Bs[0][bk * 64 + bn]),
              bSrc + (size_t)bk * PPER);
        cpa16((uint32_t)__cvta_generic_to_shared(&Bs[0][(bk + 16) * 64 + bn]),
              bSrc + (size_t)(bk + 16) * PPER);
    }
    cpa_commit();
    ra0 = __ldg(reinterpret_cast<const float4*>(aSrc + 32 + ak8));
    ra1 = __ldg(reinterpret_cast<const float4*>(aSrc + 32 + ak8 + 4));
    cpa_wait0();
    __syncthreads();

    for (int it = 0; it < NIT; it++) {
        int c = it & 1, o = c ^ 1;
        if (it + 1 < NIT) {
            #pragma unroll
            for (int j = 0; j < 4; j++) {
                As[o][(ak8 + j) * GPAD + am]     = (&ra0.x)[j];
                As[o][(ak8 + 4 + j) * GPAD + am] = (&ra1.x)[j];
            }
            int kt = (it + 1) * 32;
            if (bvalid) {
                cpa16((uint32_t)__cvta_generic_to_shared(&Bs[o][bk * 64 + bn]),
                      bSrc + (size_t)(kt + bk) * PPER);
                cpa16((uint32_t)__cvta_generic_to_shared(&Bs[o][(bk + 16) * 64 + bn]),
                      bSrc + (size_t)(kt + 16 + bk) * PPER);
            }
            cpa_commit();
            if (it + 2 < NIT) {
                ra0 = __ldg(reinterpret_cast<const float4*>(aSrc + (it + 2) * 32 + ak8));
                ra1 = __ldg(reinterpret_cast<const float4*>(aSrc + (it + 2) * 32 + ak8 + 4));
            }
        }
        #pragma unroll
        for (int k = 0; k < 32; k++) {
            float4 a4 = *reinterpret_cast<const float4*>(&As[c][k * GPAD + m0]);
            float4 b4 = *reinterpret_cast<const float4*>(&Bs[c][k * 64 + n0]);
            acc[0][0] += a4.x * b4.x; acc[0][1] += a4.x * b4.y;
            acc[0][2] += a4.x * b4.z; acc[0][3] += a4.x * b4.w;
            acc[1][0] += a4.y * b4.x; acc[1][1] += a4.y * b4.y;
            acc[1][2] += a4.y * b4.z; acc[1][3] += a4.y * b4.w;
            acc[2][0] += a4.z * b4.x; acc[2][1] += a4.z * b4.y;
            acc[2][2] += a4.z * b4.z; acc[2][3] += a4.z * b4.w;
            acc[3][0] += a4.w * b4.x; acc[3][1] += a4.w * b4.y;
            acc[3][2] += a4.w * b4.z; acc[3][3] += a4.w * b4.w;
        }
        if (it + 1 < NIT) cpa_wait0();
        __syncthreads();
    }
    #pragma unroll
    for (int j = 0; j < 4; j++) {
        int c = col0 + j;
        if (c < PPER) {
            int h = c / 52, rr = c % 52, fi = rr >> 1;
            float basef = __ldg(&bfil[h * FBB + fi]);
            float baseb = __ldg(&bbia[h * FBB + fi]);
            #pragma unroll
            for (int i = 0; i < 4; i++) {
                float v = (rr & 1) ? (baseb + acc[i][j])
                                   : (basef * (1.0f + acc[i][j]));
                g_fb[(size_t)(bm0 + m0 + i) * PPER + c] = v;
            }
        }
    }
}

// ---------------- k_main helpers (templated, static coeff indexing) ----------
template<int I0, int NI, int PAR>
__device__ __forceinline__ void conv_pass(u64* acc, const float* xcol,
                                          const u64* cdh, int p) {
    u64 cc[13];
    #pragma unroll
    for (int j = 0; j < 13; j++) cc[j] = cdh[2 * j + PAR];
    #pragma unroll
    for (int e = 0; e < 25; e++) {
        int srow = 2 * e + PAR + p;
        if (2 * e + PAR + 1 >= 50) { if (srow >= 50) srow -= 50; }
        u64 xv = *reinterpret_cast<const u64*>(xcol + srow * HIDD);
        #pragma unroll
        for (int i = 0; i < NI; i++) {
            const int dd = ((2 * (I0 + i) - (2 * e + PAR)) % 50 + 50) % 50;
            const int f  = (dd <= 25) ? dd : (50 - dd);
            ffma2(acc[i], xv, cc[f >> 1]);
        }
    }
}

template<int I0, int NI>
__device__ __forceinline__ void acc_init(u64* acc, const float* bvs, int h, int p) {
    #pragma unroll
    for (int i = 0; i < NI; i++) {
        float bv = bvs[h * 50 + 2 * (I0 + i) + p];
        acc[i] = pack2(bv, bv);
    }
}

template<int I0, int NI>
__device__ __forceinline__ void wavelet_combine(u64* acc, const float* xs,
                                                const float* __restrict__ cw,
                                                int h, int d0, int p) {
    float sgn = p ? -1.0f : 1.0f;
    int dl = d0 & 63;
    #pragma unroll
    for (int i = 0; i < NI; i++) {
        int ia = I0 + i;
        float2 e = *reinterpret_cast<const float2*>(&xs[(2 * ia)     * HIDD + d0]);
        float2 o = *reinterpret_cast<const float2*>(&xs[(2 * ia + 1) * HIDD + d0]);
        float2 w = __ldg(reinterpret_cast<const float2*>(cw + h * (25 * HDD) + ia * HDD + dl));
        float ax = 0.5f * (e.x + o.x), ay = 0.5f * (e.y + o.y);
        float dx = 0.5f * (e.x - o.x) * w.x, dy = 0.5f * (e.y - o.y) * w.y;
        float wx = ax + sgn * dx, wy = ay + sgn * dy;
        float ix = p ? o.x : e.x;
        float iy = p ? o.y : e.y;
        float fx, fy; unpack2(acc[i], fx, fy);
        acc[i] = pack2(0.7f * wx + 0.3f * fx + ix,
                       0.7f * wy + 0.3f * fy + iy);
    }
}

template<int I0, int NI>
__device__ __forceinline__ void store_rows(const u64* acc, float* xs, int d0, int p) {
    #pragma unroll
    for (int i = 0; i < NI; i++)
        *reinterpret_cast<u64*>(&xs[(2 * (I0 + i) + p) * HIDD + d0]) = acc[i];
}

// ---------------- K4: 512 threads, 2 CTAs/SM (PROVEN; unchanged from R13) ----
// smem float offsets (16B-aligned where vector-accessed):
//   xs 0:12800 | cd 12800:208 | bvs 13008:200 | fbs 13208:208
//   ctab 13416:56(pad) | gs 13472:256 | bsv 13728:256  => 13984 floats
#define SMEM_FLOATS 13984

__global__ __launch_bounds__(512, 2) void k_main(const float* __restrict__ item,
                                                 const float* __restrict__ cw,
                                                 const float* __restrict__ gamma,
                                                 const float* __restrict__ beta,
                                                 float* __restrict__ out) {
    extern __shared__ float sm[];
    float* xs   = sm;
    float* cd   = sm + 12800;
    float* bvs  = sm + 13008;
    float* fbs  = sm + 13208;
    float* ctab = sm + 13416;
    float* gs   = sm + 13472;
    float* bsv  = sm + 13728;

    int b   = blockIdx.x;
    int tid = threadIdx.x;
    const float* itemb = item + (size_t)b * SS * HIDD;

    // ---- stage: xs via cp.async (latency hidden under coeff compute) ----
    {
        uint32_t xa = (uint32_t)__cvta_generic_to_shared(xs);
        for (int i = tid; i < SS * HIDD / 4; i += 512)
            cpa16(xa + i * 16, itemb + i * 4);
        cpa_commit();
    }
    if (tid < PPER) fbs[tid] = g_fb[b * PPER + tid];
    if (tid < 50)   ctab[tid] = cospif((float)tid * (1.0f / 25.0f));
    if (tid < HIDD) { gs[tid] = gamma[tid]; bsv[tid] = beta[tid]; }
    __syncthreads();

    if (tid < 104) {
        int h = tid / 26, m = tid % 26;
        const float* fh = fbs + h * 52;
        float cacc = 0.f;
        int idx = 0;
        #pragma unroll
        for (int k = 0; k < 26; k++) {
            float w = (k == 0 || k == 25) ? 1.0f : 2.0f;
            cacc += fh[2 * k] * w * ctab[idx];
            idx += m; if (idx >= 50) idx -= 50;
        }
        reinterpret_cast<float2*>(cd)[h * 26 + m] = make_float2(cacc * 0.02f, cacc * 0.02f);
    }
    if (tid < 200) {
        int h = tid / 50, m = tid % 50;
        const float* fh = fbs + h * 52;
        float bacc = 0.f;
        int idx = 0;
        #pragma unroll
        for (int k = 0; k < 26; k++) {
            float w = (k == 0 || k == 25) ? 1.0f : 2.0f;
            bacc += fh[2 * k + 1] * w * ctab[idx];
            idx += m; if (idx >= 50) idx -= 50;
        }
        bvs[h * 50 + m] = bacc * 0.14142135623730951f;
    }
    cpa_wait0();
    __syncthreads();

    int dp = tid & 127;
    int p  = (tid >> 7) & 1;
    int rh = tid >> 8;
    int d0 = dp * 2;
    int h  = dp >> 5;

    const u64*   cdh  = reinterpret_cast<const u64*>(cd) + h * 26;
    const float* xcol = xs + d0;

    u64 acc[13];
    if (rh == 0) {
        acc_init<0, 13>(acc, bvs, h, p);
        conv_pass<0, 13, 0>(acc, xcol, cdh, p);
    } else {
        acc_init<13, 12>(acc, bvs, h, p);
        conv_pass<13, 12, 0>(acc, xcol, cdh, p);
    }
    __syncthreads();
    if (rh == 0) conv_pass<0, 13, 1>(acc, xcol, cdh, p);
    else         conv_pass<13, 12, 1>(acc, xcol, cdh, p);

    if (rh == 0) wavelet_combine<0, 13>(acc, xs, cw, h, d0, p);
    else         wavelet_combine<13, 12>(acc, xs, cw, h, d0, p);

    __syncthreads();
    if (rh == 0) store_rows<0, 13>(acc, xs, d0, p);
    else         store_rows<13, 12>(acc, xs, d0, p);
    __syncthreads();

    // ---- LayerNorm: 16 warps over 50 rows, float4 lane-consecutive ----
    int wid = tid >> 5, lane = tid & 31;
    const float4* xs4 = reinterpret_cast<const float4*>(xs);
    const float4* gs4 = reinterpret_cast<const float4*>(gs);
    const float4* bs4 = reinterpret_cast<const float4*>(bsv);
    float4* outb4 = reinterpret_cast<float4*>(out + (size_t)b * SS * HIDD);
    float4 ga = gs4[lane];
    float4 gb = gs4[32 + lane];
    float4 ba = bs4[lane];
    float4 bb = bs4[32 + lane];
    for (int t = wid; t < SS; t += 16) {
        float4 va = xs4[t * 64 + lane];
        float4 vb = xs4[t * 64 + 32 + lane];
        float s1 = va.x + va.y + va.z + va.w + vb.x + vb.y + vb.z + vb.w;
        float s2 = va.x * va.x + va.y * va.y + va.z * va.z + va.w * va.w
                 + vb.x * vb.x + vb.y * vb.y + vb.z * vb.z + vb.w * vb.w;
        #pragma unroll
        for (int off = 16; off; off >>= 1) {
            s1 += __shfl_xor_sync(0xffffffffu, s1, off);
            s2 += __shfl_xor_sync(0xffffffffu, s2, off);
        }
        float mu  = s1 * (1.0f / 256.0f);
        float var = s2 * (1.0f / 256.0f) - mu * mu;
        float rs  = rsqrtf(var + 1e-12f);
        float4 oa, ob;
        oa.x = (va.x - mu) * rs * ga.x + ba.x;
        oa.y = (va.y - mu) * rs * ga.y + ba.y;
        oa.z = (va.z - mu) * rs * ga.z + ba.z;
        oa.w = (va.w - mu) * rs * ga.w + ba.w;
        ob.x = (vb.x - mu) * rs * gb.x + bb.x;
        ob.y = (vb.y - mu) * rs * gb.y + bb.y;
        ob.z = (vb.z - mu) * rs * gb.z + bb.z;
        ob.w = (vb.w - mu) * rs * gb.w + bb.w;
        outb4[t * 64 + lane]      = oa;
        outb4[t * 64 + 32 + lane] = ob;
    }
}

// ---------------- launcher ----------------
extern "C" void kernel_launch(void* const* d_in, const int* in_sizes, int n_in,
                              void* d_out, int out_size) {
    const float* item = (const float*)d_in[0];
    const float* attr = (const float*)d_in[1];
    const float* cw   = (const float*)d_in[2];
    const float* bfil = (const float*)d_in[3];
    const float* bbia = (const float*)d_in[4];
    const float* w1   = (const float*)d_in[5];
    const float* b1   = (const float*)d_in[6];
    const float* w2   = (const float*)d_in[7];
    const float* b2   = (const float*)d_in[8];
    const float* gam  = (const float*)d_in[9];
    const float* bet  = (const float*)d_in[10];
    float* out = (float*)d_out;

    cudaFuncSetAttribute(k_main, cudaFuncAttributeMaxDynamicSharedMemorySize,
                         SMEM_FLOATS * (int)sizeof(float));

    k_ctx<<<BB * (HIDD / 4) / 256, 256>>>(attr);
    k_g1<<<dim3(BB / 64, HIDD / 64), 256>>>(w1, b1);
    k_g2<<<dim3(BB / 64, 4), 256>>>(w2, b2, bfil, bbia);
    k_main<<<BB, 512, SMEM_FLOATS * (int)sizeof(float)>>>(item, cw, gam, bet, out);
}